// round 6
// baseline (speedup 1.0000x reference)
#include <cuda_runtime.h>
#include <cuda_bf16.h>
#include <math_constants.h>
#include <cstdint>
#include <cstddef>

// Problem constants (fixed by the reference)
#define NN 20000
#define EE 320000
#define D_IN 256
#define LL 4
#define HH 4
#define UU 64
#define HID 256
#define OUT_D 64

// ---------------------------------------------------------------------------
// Static device scratch (no runtime allocation allowed)
// ---------------------------------------------------------------------------
__device__ float g_h[(size_t)NN * HID];
__device__ float g_tmp[(size_t)NN * HID];
__device__ float g_zl[(size_t)NN * HID];
__device__ float g_zr[(size_t)NN * HID];
__device__ float g_dense[(size_t)NN * 4 * HID];
__device__ int   g_deg[NN];
__device__ int   g_rowptr[NN + 1];
__device__ int   g_cursor[NN];
__device__ int   g_srcs[EE];

// ---------------------------------------------------------------------------
// Small helpers
// ---------------------------------------------------------------------------
__device__ __forceinline__ float gelu_f(float x) {
    float x3 = x * x * x;
    float z  = 0.7978845608028654f * (x + 0.044715f * x3);
    float e  = __expf(2.0f * z);
    float t  = 1.0f - 2.0f / (e + 1.0f);   // tanh(z)
    return 0.5f * x * (1.0f + t);
}

// ---------------------------------------------------------------------------
// CSR build
// ---------------------------------------------------------------------------
__global__ void zero_deg_kernel() {
    int i = blockIdx.x * blockDim.x + threadIdx.x;
    if (i < NN) g_deg[i] = 0;
}

__global__ void hist_kernel(const int* __restrict__ edges) {
    int e = blockIdx.x * blockDim.x + threadIdx.x;
    if (e < EE) atomicAdd(&g_deg[edges[2 * e]], 1);
}

__global__ void scan_kernel() {
    __shared__ int sh[1024];
    const int t = threadIdx.x;
    const int CH = (NN + 1023) / 1024;   // 20
    const int base = t * CH;
    int local = 0;
    for (int i = 0; i < CH; i++) {
        int idx = base + i;
        if (idx < NN) local += g_deg[idx];
    }
    sh[t] = local;
    __syncthreads();
    for (int off = 1; off < 1024; off <<= 1) {
        int add = (t >= off) ? sh[t - off] : 0;
        __syncthreads();
        sh[t] += add;
        __syncthreads();
    }
    int run = (t > 0) ? sh[t - 1] : 0;   // exclusive prefix
    for (int i = 0; i < CH; i++) {
        int idx = base + i;
        if (idx < NN) {
            g_rowptr[idx] = run;
            g_cursor[idx] = run;
            run += g_deg[idx];
        }
    }
    if (t == 1023) g_rowptr[NN] = run;
}

__global__ void scatter_kernel(const int* __restrict__ edges) {
    int e = blockIdx.x * blockDim.x + threadIdx.x;
    if (e < EE) {
        int d = edges[2 * e];
        int s = edges[2 * e + 1];
        int p = atomicAdd(&g_cursor[d], 1);
        g_srcs[p] = s;
    }
}

// ---------------------------------------------------------------------------
// LayerNorm: one warp per row of 256
// ---------------------------------------------------------------------------
__global__ void ln_kernel(const float* __restrict__ in,
                          const float* __restrict__ gw,
                          const float* __restrict__ bw,
                          float* __restrict__ out) {
    int warp = blockIdx.x * (blockDim.x >> 5) + (threadIdx.x >> 5);
    int lane = threadIdx.x & 31;
    if (warp >= NN) return;
    const float4* row = (const float4*)(in + (size_t)warp * HID);
    float4 v0 = row[lane];
    float4 v1 = row[lane + 32];
    float s = v0.x + v0.y + v0.z + v0.w + v1.x + v1.y + v1.z + v1.w;
    float q = v0.x * v0.x + v0.y * v0.y + v0.z * v0.z + v0.w * v0.w +
              v1.x * v1.x + v1.y * v1.y + v1.z * v1.z + v1.w * v1.w;
#pragma unroll
    for (int off = 16; off > 0; off >>= 1) {
        s += __shfl_xor_sync(0xFFFFFFFFu, s, off);
        q += __shfl_xor_sync(0xFFFFFFFFu, q, off);
    }
    float mean = s * (1.0f / 256.0f);
    float var  = q * (1.0f / 256.0f) - mean * mean;
    float rstd = rsqrtf(var + 1e-3f);

    const float4* g4 = (const float4*)gw;
    const float4* b4 = (const float4*)bw;
    float4* orow = (float4*)(out + (size_t)warp * HID);

    float4 gg = g4[lane], bb = b4[lane], o;
    o.x = (v0.x - mean) * rstd * gg.x + bb.x;
    o.y = (v0.y - mean) * rstd * gg.y + bb.y;
    o.z = (v0.z - mean) * rstd * gg.z + bb.z;
    o.w = (v0.w - mean) * rstd * gg.w + bb.w;
    orow[lane] = o;

    gg = g4[lane + 32]; bb = b4[lane + 32];
    o.x = (v1.x - mean) * rstd * gg.x + bb.x;
    o.y = (v1.y - mean) * rstd * gg.y + bb.y;
    o.z = (v1.z - mean) * rstd * gg.z + bb.z;
    o.w = (v1.w - mean) * rstd * gg.w + bb.w;
    orow[lane + 32] = o;
}

// ---------------------------------------------------------------------------
// Generic fp32 SIMT GEMM: C[M,Ncols] = A[M,256] * B[256,Ncols] (+bias)(+gelu)
// ---------------------------------------------------------------------------
template <int BM, int BN, int BK, int TM, int TN, int ACT>
__global__ void __launch_bounds__(256)
gemm_kernel(const float* __restrict__ A, const float* __restrict__ B,
            const float* __restrict__ bias, float* __restrict__ C,
            int M, int Ncols) {
    constexpr int K = 256;
    __shared__ float As[BK][BM + 4];
    __shared__ float Bs[BK][BN];

    const int tid = threadIdx.x;
    const int m0 = blockIdx.y * BM;
    const int n0 = blockIdx.x * BN;
    const int tx = tid & 15;   // 16 column groups
    const int ty = tid >> 4;   // 16 row groups

    float acc[TM][TN];
#pragma unroll
    for (int i = 0; i < TM; i++)
#pragma unroll
        for (int j = 0; j < TN; j++) acc[i][j] = 0.0f;

    constexpr int AF4 = BM * BK / 4;
    constexpr int BF4 = BK * BN / 4;
    constexpr int NF4A = BK / 4;

    for (int k0 = 0; k0 < K; k0 += BK) {
#pragma unroll
        for (int p = 0; p < AF4 / 256; p++) {
            int i = tid + p * 256;
            int row = i / NF4A;
            int kq  = i % NF4A;
            int gr = m0 + row;
            float4 v = make_float4(0.f, 0.f, 0.f, 0.f);
            if (gr < M) v = *(const float4*)(A + (size_t)gr * K + k0 + kq * 4);
            As[kq * 4 + 0][row] = v.x;
            As[kq * 4 + 1][row] = v.y;
            As[kq * 4 + 2][row] = v.z;
            As[kq * 4 + 3][row] = v.w;
        }
#pragma unroll
        for (int p = 0; p < BF4 / 256; p++) {
            int i = tid + p * 256;
            int k  = i / (BN / 4);
            int c4 = i % (BN / 4);
            *(float4*)&Bs[k][c4 * 4] =
                *(const float4*)(B + (size_t)(k0 + k) * Ncols + n0 + c4 * 4);
        }
        __syncthreads();
#pragma unroll
        for (int kk = 0; kk < BK; kk++) {
            float a[TM], b[TN];
#pragma unroll
            for (int i = 0; i < TM; i += 4)
                *(float4*)&a[i] = *(const float4*)&As[kk][ty * TM + i];
#pragma unroll
            for (int j = 0; j < TN; j += 4)
                *(float4*)&b[j] = *(const float4*)&Bs[kk][tx * TN + j];
#pragma unroll
            for (int i = 0; i < TM; i++)
#pragma unroll
                for (int j = 0; j < TN; j++)
                    acc[i][j] = fmaf(a[i], b[j], acc[i][j]);
        }
        __syncthreads();
    }

#pragma unroll
    for (int i = 0; i < TM; i++) {
        int gr = m0 + ty * TM + i;
        if (gr < M) {
#pragma unroll
            for (int j = 0; j < TN; j++) {
                int gc = n0 + tx * TN + j;
                float v = acc[i][j];
                if (bias) v += bias[gc];
                if (ACT == 1) v = gelu_f(v);
                C[(size_t)gr * Ncols + gc] = v;
            }
        }
    }
}

// ---------------------------------------------------------------------------
// GATv2 fused edge kernel: one warp per (node, head), online softmax over
// incoming edges. out = agg + xres (residual on the LN'd input).
// ---------------------------------------------------------------------------
__global__ void gat_edge_kernel(const float* __restrict__ zl,
                                const float* __restrict__ zr,
                                const float* __restrict__ att_l,
                                const float* __restrict__ xres,
                                float* __restrict__ out) {
    int wid  = blockIdx.x * (blockDim.x >> 5) + (threadIdx.x >> 5);
    int lane = threadIdx.x & 31;
    if (wid >= NN * HH) return;
    int node = wid >> 2;
    int head = wid & 3;
    int off  = head * UU + lane * 2;

    float2 zl2 = *(const float2*)(zl + (size_t)node * HID + off);
    float2 a2  = *(const float2*)(att_l + off);

    float m = -CUDART_INF_F;
    float den = 0.0f;
    float2 acc = make_float2(0.0f, 0.0f);

    int j0 = g_rowptr[node];
    int j1 = g_rowptr[node + 1];
    for (int j = j0; j < j1; j++) {
        int s = g_srcs[j];
        float2 z2 = *(const float2*)(zr + (size_t)s * HID + off);
        float fx = zl2.x + z2.x; fx = fx > 0.0f ? fx : 0.2f * fx;
        float fy = zl2.y + z2.y; fy = fy > 0.0f ? fy : 0.2f * fy;
        float p = fx * a2.x + fy * a2.y;
#pragma unroll
        for (int o = 16; o > 0; o >>= 1)
            p += __shfl_xor_sync(0xFFFFFFFFu, p, o);
        float mn = fmaxf(m, p);
        float sc = __expf(m - mn);    // 0 when m == -inf (first edge)
        float w  = __expf(p - mn);
        den   = den * sc + w;
        acc.x = acc.x * sc + w * z2.x;
        acc.y = acc.y * sc + w * z2.y;
        m = mn;
    }
    float inv = 1.0f / (den + 1e-9f);
    float2 xr2 = *(const float2*)(xres + (size_t)node * HID + off);
    float2 o;
    o.x = acc.x * inv + xr2.x;
    o.y = acc.y * inv + xr2.y;
    *(float2*)(out + (size_t)node * HID + off) = o;
}

// ---------------------------------------------------------------------------
// Reduce the 4 gelu chunks of the dense output + residual
// ---------------------------------------------------------------------------
__global__ void reduce_dense_kernel(const float* __restrict__ d,
                                    const float* __restrict__ xr,
                                    float* __restrict__ out) {
    int idx = blockIdx.x * blockDim.x + threadIdx.x;
    if (idx >= NN * HID) return;
    int n = idx >> 8;
    int j = idx & 255;
    const float* row = d + (size_t)n * 1024 + j;
    out[idx] = xr[idx] + row[0] + row[256] + row[512] + row[768];
}

// ---------------------------------------------------------------------------
// Launch
// ---------------------------------------------------------------------------
extern "C" void kernel_launch(void* const* d_in, const int* in_sizes, int n_in,
                              void* d_out, int out_size) {
    const float* x       = (const float*)d_in[0];
    const float* head_W  = (const float*)d_in[1];
    const float* head_b  = (const float*)d_in[2];
    const float* ng_g    = (const float*)d_in[3];
    const float* ng_b    = (const float*)d_in[4];
    const float* Wl      = (const float*)d_in[5];
    const float* Wr      = (const float*)d_in[6];
    const float* att     = (const float*)d_in[7];
    const float* nd_g    = (const float*)d_in[8];
    const float* nd_b    = (const float*)d_in[9];
    const float* dense_W = (const float*)d_in[10];
    const float* dense_b = (const float*)d_in[11];
    const float* tail_W  = (const float*)d_in[12];
    const float* tail_b  = (const float*)d_in[13];
    const int*   edges   = (const int*)d_in[14];
    float* out = (float*)d_out;

    float *p_h, *p_tmp, *p_zl, *p_zr, *p_dense;
    cudaGetSymbolAddress((void**)&p_h, g_h);
    cudaGetSymbolAddress((void**)&p_tmp, g_tmp);
    cudaGetSymbolAddress((void**)&p_zl, g_zl);
    cudaGetSymbolAddress((void**)&p_zr, g_zr);
    cudaGetSymbolAddress((void**)&p_dense, g_dense);

    // ---- CSR build ----
    zero_deg_kernel<<<(NN + 255) / 256, 256>>>();
    hist_kernel<<<(EE + 255) / 256, 256>>>(edges);
    scan_kernel<<<1, 1024>>>();
    scatter_kernel<<<(EE + 255) / 256, 256>>>(edges);

    const int MY = (NN + 127) / 128;   // GEMM row blocks

    // ---- head: h = x @ head_W + head_b ----
    gemm_kernel<128, 128, 16, 8, 8, 0>
        <<<dim3(HID / 128, MY), 256>>>(x, head_W, head_b, p_h, NN, HID);

    const int LN_BLOCKS = (NN + 7) / 8;     // 8 warps/block
    const int EDGE_BLOCKS = (NN * HH + 7) / 8;

    for (int l = 0; l < LL; l++) {
        // LN1
        ln_kernel<<<LN_BLOCKS, 256>>>(p_h, ng_g + l * HID, ng_b + l * HID, p_tmp);
        // zl, zr
        gemm_kernel<128, 128, 16, 8, 8, 0>
            <<<dim3(HID / 128, MY), 256>>>(p_tmp, Wl + (size_t)l * HID * HID,
                                           nullptr, p_zl, NN, HID);
        gemm_kernel<128, 128, 16, 8, 8, 0>
            <<<dim3(HID / 128, MY), 256>>>(p_tmp, Wr + (size_t)l * HID * HID,
                                           nullptr, p_zr, NN, HID);
        // fused attention + aggregation + residual
        gat_edge_kernel<<<EDGE_BLOCKS, 256>>>(p_zl, p_zr, att + l * HH * UU,
                                              p_tmp, p_h);
        // LN2
        ln_kernel<<<LN_BLOCKS, 256>>>(p_h, nd_g + l * HID, nd_b + l * HID, p_tmp);
        // dense with fused gelu
        gemm_kernel<128, 128, 16, 8, 8, 1>
            <<<dim3(4 * HID / 128, MY), 256>>>(p_tmp,
                                               dense_W + (size_t)l * HID * 4 * HID,
                                               dense_b + (size_t)l * 4 * HID,
                                               p_dense, NN, 4 * HID);
        // chunk-sum + residual
        reduce_dense_kernel<<<(NN * HID + 255) / 256, 256>>>(p_dense, p_tmp, p_h);
    }

    // ---- tail: out = h @ tail_W + tail_b ----
    gemm_kernel<128, 64, 16, 8, 4, 0>
        <<<dim3(OUT_D / 64, MY), 256>>>(p_h, tail_W, tail_b, out, NN, OUT_D);
}

// round 7
// speedup vs baseline: 1.0003x; 1.0003x over previous
#include <cuda_runtime.h>
#include <cuda_bf16.h>
#include <math_constants.h>
#include <cstdint>
#include <cstddef>

// Problem constants (fixed by the reference)
#define NN 20000
#define EE 320000
#define D_IN 256
#define LL 4
#define HH 4
#define UU 64
#define HID 256
#define OUT_D 64

// ---------------------------------------------------------------------------
// Static device scratch (no runtime allocation allowed)
// ---------------------------------------------------------------------------
__device__ float g_h[(size_t)NN * HID];
__device__ float g_tmp[(size_t)NN * HID];
__device__ float g_zl[(size_t)NN * HID];
__device__ float g_zr[(size_t)NN * HID];
__device__ float g_dense[(size_t)NN * 4 * HID];
__device__ int   g_deg[NN];
__device__ int   g_rowptr[NN + 1];
__device__ int   g_cursor[NN];
__device__ int   g_srcs[EE];

// ---------------------------------------------------------------------------
// Small helpers
// ---------------------------------------------------------------------------
__device__ __forceinline__ float gelu_f(float x) {
    float x3 = x * x * x;
    float z  = 0.7978845608028654f * (x + 0.044715f * x3);
    float e  = __expf(2.0f * z);
    float t  = 1.0f - 2.0f / (e + 1.0f);   // tanh(z)
    return 0.5f * x * (1.0f + t);
}

// ---------------------------------------------------------------------------
// CSR build
// ---------------------------------------------------------------------------
__global__ void zero_deg_kernel() {
    int i = blockIdx.x * blockDim.x + threadIdx.x;
    if (i < NN) g_deg[i] = 0;
}

__global__ void hist_kernel(const int* __restrict__ edges) {
    int e = blockIdx.x * blockDim.x + threadIdx.x;
    if (e < EE) atomicAdd(&g_deg[edges[2 * e]], 1);
}

__global__ void scan_kernel() {
    __shared__ int sh[1024];
    const int t = threadIdx.x;
    const int CH = (NN + 1023) / 1024;   // 20
    const int base = t * CH;
    int local = 0;
    for (int i = 0; i < CH; i++) {
        int idx = base + i;
        if (idx < NN) local += g_deg[idx];
    }
    sh[t] = local;
    __syncthreads();
    for (int off = 1; off < 1024; off <<= 1) {
        int add = (t >= off) ? sh[t - off] : 0;
        __syncthreads();
        sh[t] += add;
        __syncthreads();
    }
    int run = (t > 0) ? sh[t - 1] : 0;   // exclusive prefix
    for (int i = 0; i < CH; i++) {
        int idx = base + i;
        if (idx < NN) {
            g_rowptr[idx] = run;
            g_cursor[idx] = run;
            run += g_deg[idx];
        }
    }
    if (t == 1023) g_rowptr[NN] = run;
}

__global__ void scatter_kernel(const int* __restrict__ edges) {
    int e = blockIdx.x * blockDim.x + threadIdx.x;
    if (e < EE) {
        int d = edges[2 * e];
        int s = edges[2 * e + 1];
        int p = atomicAdd(&g_cursor[d], 1);
        g_srcs[p] = s;
    }
}

// ---------------------------------------------------------------------------
// LayerNorm: one warp per row of 256
// ---------------------------------------------------------------------------
__global__ void ln_kernel(const float* __restrict__ in,
                          const float* __restrict__ gw,
                          const float* __restrict__ bw,
                          float* __restrict__ out) {
    int warp = blockIdx.x * (blockDim.x >> 5) + (threadIdx.x >> 5);
    int lane = threadIdx.x & 31;
    if (warp >= NN) return;
    const float4* row = (const float4*)(in + (size_t)warp * HID);
    float4 v0 = row[lane];
    float4 v1 = row[lane + 32];
    float s = v0.x + v0.y + v0.z + v0.w + v1.x + v1.y + v1.z + v1.w;
    float q = v0.x * v0.x + v0.y * v0.y + v0.z * v0.z + v0.w * v0.w +
              v1.x * v1.x + v1.y * v1.y + v1.z * v1.z + v1.w * v1.w;
#pragma unroll
    for (int off = 16; off > 0; off >>= 1) {
        s += __shfl_xor_sync(0xFFFFFFFFu, s, off);
        q += __shfl_xor_sync(0xFFFFFFFFu, q, off);
    }
    float mean = s * (1.0f / 256.0f);
    float var  = q * (1.0f / 256.0f) - mean * mean;
    float rstd = rsqrtf(var + 1e-3f);

    const float4* g4 = (const float4*)gw;
    const float4* b4 = (const float4*)bw;
    float4* orow = (float4*)(out + (size_t)warp * HID);

    float4 gg = g4[lane], bb = b4[lane], o;
    o.x = (v0.x - mean) * rstd * gg.x + bb.x;
    o.y = (v0.y - mean) * rstd * gg.y + bb.y;
    o.z = (v0.z - mean) * rstd * gg.z + bb.z;
    o.w = (v0.w - mean) * rstd * gg.w + bb.w;
    orow[lane] = o;

    gg = g4[lane + 32]; bb = b4[lane + 32];
    o.x = (v1.x - mean) * rstd * gg.x + bb.x;
    o.y = (v1.y - mean) * rstd * gg.y + bb.y;
    o.z = (v1.z - mean) * rstd * gg.z + bb.z;
    o.w = (v1.w - mean) * rstd * gg.w + bb.w;
    orow[lane + 32] = o;
}

// ---------------------------------------------------------------------------
// Generic fp32 SIMT GEMM: C[M,Ncols] = A[M,256] * B[256,Ncols] (+bias)(+gelu)
// ---------------------------------------------------------------------------
template <int BM, int BN, int BK, int TM, int TN, int ACT>
__global__ void __launch_bounds__(256)
gemm_kernel(const float* __restrict__ A, const float* __restrict__ B,
            const float* __restrict__ bias, float* __restrict__ C,
            int M, int Ncols) {
    constexpr int K = 256;
    __shared__ float As[BK][BM + 4];
    __shared__ float Bs[BK][BN];

    const int tid = threadIdx.x;
    const int m0 = blockIdx.y * BM;
    const int n0 = blockIdx.x * BN;
    const int tx = tid & 15;   // 16 column groups
    const int ty = tid >> 4;   // 16 row groups

    float acc[TM][TN];
#pragma unroll
    for (int i = 0; i < TM; i++)
#pragma unroll
        for (int j = 0; j < TN; j++) acc[i][j] = 0.0f;

    constexpr int AF4 = BM * BK / 4;
    constexpr int BF4 = BK * BN / 4;
    constexpr int NF4A = BK / 4;

    for (int k0 = 0; k0 < K; k0 += BK) {
#pragma unroll
        for (int p = 0; p < AF4 / 256; p++) {
            int i = tid + p * 256;
            int row = i / NF4A;
            int kq  = i % NF4A;
            int gr = m0 + row;
            float4 v = make_float4(0.f, 0.f, 0.f, 0.f);
            if (gr < M) v = *(const float4*)(A + (size_t)gr * K + k0 + kq * 4);
            As[kq * 4 + 0][row] = v.x;
            As[kq * 4 + 1][row] = v.y;
            As[kq * 4 + 2][row] = v.z;
            As[kq * 4 + 3][row] = v.w;
        }
#pragma unroll
        for (int p = 0; p < BF4 / 256; p++) {
            int i = tid + p * 256;
            int k  = i / (BN / 4);
            int c4 = i % (BN / 4);
            *(float4*)&Bs[k][c4 * 4] =
                *(const float4*)(B + (size_t)(k0 + k) * Ncols + n0 + c4 * 4);
        }
        __syncthreads();
#pragma unroll
        for (int kk = 0; kk < BK; kk++) {
            float a[TM], b[TN];
#pragma unroll
            for (int i = 0; i < TM; i += 4)
                *(float4*)&a[i] = *(const float4*)&As[kk][ty * TM + i];
#pragma unroll
            for (int j = 0; j < TN; j += 4)
                *(float4*)&b[j] = *(const float4*)&Bs[kk][tx * TN + j];
#pragma unroll
            for (int i = 0; i < TM; i++)
#pragma unroll
                for (int j = 0; j < TN; j++)
                    acc[i][j] = fmaf(a[i], b[j], acc[i][j]);
        }
        __syncthreads();
    }

#pragma unroll
    for (int i = 0; i < TM; i++) {
        int gr = m0 + ty * TM + i;
        if (gr < M) {
#pragma unroll
            for (int j = 0; j < TN; j++) {
                int gc = n0 + tx * TN + j;
                float v = acc[i][j];
                if (bias) v += bias[gc];
                if (ACT == 1) v = gelu_f(v);
                C[(size_t)gr * Ncols + gc] = v;
            }
        }
    }
}

// ---------------------------------------------------------------------------
// GATv2 fused edge kernel: one warp per (node, head), online softmax over
// incoming edges. out = agg + xres (residual on the LN'd input).
// ---------------------------------------------------------------------------
__global__ void gat_edge_kernel(const float* __restrict__ zl,
                                const float* __restrict__ zr,
                                const float* __restrict__ att_l,
                                const float* __restrict__ xres,
                                float* __restrict__ out) {
    int wid  = blockIdx.x * (blockDim.x >> 5) + (threadIdx.x >> 5);
    int lane = threadIdx.x & 31;
    if (wid >= NN * HH) return;
    int node = wid >> 2;
    int head = wid & 3;
    int off  = head * UU + lane * 2;

    float2 zl2 = *(const float2*)(zl + (size_t)node * HID + off);
    float2 a2  = *(const float2*)(att_l + off);

    float m = -CUDART_INF_F;
    float den = 0.0f;
    float2 acc = make_float2(0.0f, 0.0f);

    int j0 = g_rowptr[node];
    int j1 = g_rowptr[node + 1];
    for (int j = j0; j < j1; j++) {
        int s = g_srcs[j];
        float2 z2 = *(const float2*)(zr + (size_t)s * HID + off);
        float fx = zl2.x + z2.x; fx = fx > 0.0f ? fx : 0.2f * fx;
        float fy = zl2.y + z2.y; fy = fy > 0.0f ? fy : 0.2f * fy;
        float p = fx * a2.x + fy * a2.y;
#pragma unroll
        for (int o = 16; o > 0; o >>= 1)
            p += __shfl_xor_sync(0xFFFFFFFFu, p, o);
        float mn = fmaxf(m, p);
        float sc = __expf(m - mn);    // 0 when m == -inf (first edge)
        float w  = __expf(p - mn);
        den   = den * sc + w;
        acc.x = acc.x * sc + w * z2.x;
        acc.y = acc.y * sc + w * z2.y;
        m = mn;
    }
    float inv = 1.0f / (den + 1e-9f);
    float2 xr2 = *(const float2*)(xres + (size_t)node * HID + off);
    float2 o;
    o.x = acc.x * inv + xr2.x;
    o.y = acc.y * inv + xr2.y;
    *(float2*)(out + (size_t)node * HID + off) = o;
}

// ---------------------------------------------------------------------------
// Reduce the 4 gelu chunks of the dense output + residual
// ---------------------------------------------------------------------------
__global__ void reduce_dense_kernel(const float* __restrict__ d,
                                    const float* __restrict__ xr,
                                    float* __restrict__ out) {
    int idx = blockIdx.x * blockDim.x + threadIdx.x;
    if (idx >= NN * HID) return;
    int n = idx >> 8;
    int j = idx & 255;
    const float* row = d + (size_t)n * 1024 + j;
    out[idx] = xr[idx] + row[0] + row[256] + row[512] + row[768];
}

// ---------------------------------------------------------------------------
// Launch
// ---------------------------------------------------------------------------
extern "C" void kernel_launch(void* const* d_in, const int* in_sizes, int n_in,
                              void* d_out, int out_size) {
    const float* x       = (const float*)d_in[0];
    const float* head_W  = (const float*)d_in[1];
    const float* head_b  = (const float*)d_in[2];
    const float* ng_g    = (const float*)d_in[3];
    const float* ng_b    = (const float*)d_in[4];
    const float* Wl      = (const float*)d_in[5];
    const float* Wr      = (const float*)d_in[6];
    const float* att     = (const float*)d_in[7];
    const float* nd_g    = (const float*)d_in[8];
    const float* nd_b    = (const float*)d_in[9];
    const float* dense_W = (const float*)d_in[10];
    const float* dense_b = (const float*)d_in[11];
    const float* tail_W  = (const float*)d_in[12];
    const float* tail_b  = (const float*)d_in[13];
    const int*   edges   = (const int*)d_in[14];
    float* out = (float*)d_out;

    float *p_h, *p_tmp, *p_zl, *p_zr, *p_dense;
    cudaGetSymbolAddress((void**)&p_h, g_h);
    cudaGetSymbolAddress((void**)&p_tmp, g_tmp);
    cudaGetSymbolAddress((void**)&p_zl, g_zl);
    cudaGetSymbolAddress((void**)&p_zr, g_zr);
    cudaGetSymbolAddress((void**)&p_dense, g_dense);

    // ---- CSR build ----
    zero_deg_kernel<<<(NN + 255) / 256, 256>>>();
    hist_kernel<<<(EE + 255) / 256, 256>>>(edges);
    scan_kernel<<<1, 1024>>>();
    scatter_kernel<<<(EE + 255) / 256, 256>>>(edges);

    const int MY = (NN + 127) / 128;   // GEMM row blocks

    // ---- head: h = x @ head_W + head_b ----
    gemm_kernel<128, 128, 16, 8, 8, 0>
        <<<dim3(HID / 128, MY), 256>>>(x, head_W, head_b, p_h, NN, HID);

    const int LN_BLOCKS = (NN + 7) / 8;     // 8 warps/block
    const int EDGE_BLOCKS = (NN * HH + 7) / 8;

    for (int l = 0; l < LL; l++) {
        // LN1
        ln_kernel<<<LN_BLOCKS, 256>>>(p_h, ng_g + l * HID, ng_b + l * HID, p_tmp);
        // zl, zr
        gemm_kernel<128, 128, 16, 8, 8, 0>
            <<<dim3(HID / 128, MY), 256>>>(p_tmp, Wl + (size_t)l * HID * HID,
                                           nullptr, p_zl, NN, HID);
        gemm_kernel<128, 128, 16, 8, 8, 0>
            <<<dim3(HID / 128, MY), 256>>>(p_tmp, Wr + (size_t)l * HID * HID,
                                           nullptr, p_zr, NN, HID);
        // fused attention + aggregation + residual
        gat_edge_kernel<<<EDGE_BLOCKS, 256>>>(p_zl, p_zr, att + l * HH * UU,
                                              p_tmp, p_h);
        // LN2
        ln_kernel<<<LN_BLOCKS, 256>>>(p_h, nd_g + l * HID, nd_b + l * HID, p_tmp);
        // dense with fused gelu
        gemm_kernel<128, 128, 16, 8, 8, 1>
            <<<dim3(4 * HID / 128, MY), 256>>>(p_tmp,
                                               dense_W + (size_t)l * HID * 4 * HID,
                                               dense_b + (size_t)l * 4 * HID,
                                               p_dense, NN, 4 * HID);
        // chunk-sum + residual
        reduce_dense_kernel<<<(NN * HID + 255) / 256, 256>>>(p_dense, p_tmp, p_h);
    }

    // ---- tail: out = h @ tail_W + tail_b ----
    gemm_kernel<128, 64, 16, 8, 4, 0>
        <<<dim3(OUT_D / 64, MY), 256>>>(p_h, tail_W, tail_b, out, NN, OUT_D);
}